// round 1
// baseline (speedup 1.0000x reference)
#include <cuda_runtime.h>
#include <math.h>

#define NSWEEP 9

// scratch: Y matrices (4096 x 20 x 20)
__device__ float g_Y[4096 * 400];

// ---------------------------------------------------------------------------
// Kernel A: per-batch centering + Gram + Gaussian kernel + Y = W^T K W
// grid 4096, block 256, dynamic smem 93696 B
// ---------------------------------------------------------------------------
__global__ __launch_bounds__(256) void gram_kernel(const float* __restrict__ x,
                                                   const float* __restrict__ W) {
  extern __shared__ float sm[];
  float* xm  = sm;            // 64 x 260 (padded row-major)
  float* KK  = sm + 16640;    // 64 x 65
  float* Wsm = sm + 20800;    // 64 x 20
  float* Tsm = sm + 22080;    // 64 x 20
  float* sq  = sm + 23360;    // 64

  const int b    = blockIdx.x;
  const int tid  = threadIdx.x;
  const int warp = tid >> 5;
  const int lane = tid & 31;

  for (int i = tid; i < 64 * 20; i += 256) Wsm[i] = W[i];

  // ---- load x[b], subtract per-row mean, store to padded smem ----
  const float* xb = x + (size_t)b * (64 * 256);
#pragma unroll
  for (int r8 = 0; r8 < 8; r8++) {
    const int r = warp * 8 + r8;
    const float4* row = (const float4*)(xb + r * 256);
    float4 v0 = row[lane];
    float4 v1 = row[lane + 32];
    float s = v0.x + v0.y + v0.z + v0.w + v1.x + v1.y + v1.z + v1.w;
    s += __shfl_xor_sync(0xffffffffu, s, 16);
    s += __shfl_xor_sync(0xffffffffu, s, 8);
    s += __shfl_xor_sync(0xffffffffu, s, 4);
    s += __shfl_xor_sync(0xffffffffu, s, 2);
    s += __shfl_xor_sync(0xffffffffu, s, 1);
    const float m = s * (1.0f / 256.0f);
    v0.x -= m; v0.y -= m; v0.z -= m; v0.w -= m;
    v1.x -= m; v1.y -= m; v1.z -= m; v1.w -= m;
    float4* dst = (float4*)(xm + r * 260);
    dst[lane]      = v0;
    dst[lane + 32] = v1;
  }
  __syncthreads();

  // ---- Gram: thread (tx,ty) computes gram[tx+16i][ty+16j], 4x4 tile ----
  const int tx = tid & 15;
  const int ty = tid >> 4;
  float acc[4][4];
#pragma unroll
  for (int i = 0; i < 4; i++)
#pragma unroll
    for (int j = 0; j < 4; j++) acc[i][j] = 0.f;

#pragma unroll 2
  for (int k = 0; k < 256; k += 4) {
    float4 a[4], bb[4];
#pragma unroll
    for (int i = 0; i < 4; i++)
      a[i] = *(const float4*)(xm + (tx + 16 * i) * 260 + k);
#pragma unroll
    for (int j = 0; j < 4; j++)
      bb[j] = *(const float4*)(xm + (ty + 16 * j) * 260 + k);
#pragma unroll
    for (int i = 0; i < 4; i++)
#pragma unroll
      for (int j = 0; j < 4; j++) {
        acc[i][j] = fmaf(a[i].x, bb[j].x, acc[i][j]);
        acc[i][j] = fmaf(a[i].y, bb[j].y, acc[i][j]);
        acc[i][j] = fmaf(a[i].z, bb[j].z, acc[i][j]);
        acc[i][j] = fmaf(a[i].w, bb[j].w, acc[i][j]);
      }
  }
#pragma unroll
  for (int i = 0; i < 4; i++)
#pragma unroll
    for (int j = 0; j < 4; j++)
      KK[(tx + 16 * i) * 65 + (ty + 16 * j)] = acc[i][j];
  __syncthreads();

  if (tid < 64) sq[tid] = KK[tid * 65 + tid];
  __syncthreads();

  // ---- K = exp(-50 * d2), in place ----
  for (int e = tid; e < 4096; e += 256) {
    const int c = e >> 6, d = e & 63;
    const float g = KK[c * 65 + d];
    float d2 = sq[c] + sq[d] - 2.f * g;
    d2 = fmaxf(d2, 0.f) * (1.0f / 256.0f);
    KK[c * 65 + d] = __expf(-50.f * d2);
  }
  __syncthreads();

  // ---- T = K * W (64x20): thread handles row c=tid>>2, 5 cols ----
  {
    const int c  = tid >> 2;
    const int d0 = (tid & 3) * 5;
    float t0 = 0, t1 = 0, t2 = 0, t3 = 0, t4 = 0;
    for (int k = 0; k < 64; k++) {
      const float kv = KK[c * 65 + k];
      const float* wr = Wsm + k * 20 + d0;
      t0 = fmaf(kv, wr[0], t0);
      t1 = fmaf(kv, wr[1], t1);
      t2 = fmaf(kv, wr[2], t2);
      t3 = fmaf(kv, wr[3], t3);
      t4 = fmaf(kv, wr[4], t4);
    }
    float* tr = Tsm + c * 20 + d0;
    tr[0] = t0; tr[1] = t1; tr[2] = t2; tr[3] = t3; tr[4] = t4;
  }
  __syncthreads();

  // ---- Y = W^T * T (20x20) -> global scratch ----
  for (int o = tid; o < 400; o += 256) {
    const int e = o / 20;
    const int f = o - 20 * e;
    float y = 0.f;
    for (int c = 0; c < 64; c++)
      y = fmaf(Wsm[c * 20 + e], Tsm[c * 20 + f], y);
    g_Y[(size_t)b * 400 + o] = y;
  }
}

// ---------------------------------------------------------------------------
// Kernel B: one warp per batch — parallel Jacobi eigendecomposition of Y,
// M = U diag(log(max(S,eps))) U^T, triu -> linear head.
// grid 512, block 256 (8 warps)
// ---------------------------------------------------------------------------
__global__ __launch_bounds__(256) void eig_kernel(const float* __restrict__ lin_w,
                                                  const float* __restrict__ lin_b,
                                                  float* __restrict__ out) {
  __shared__ float sA[8][420];   // 20 x 21 padded
  __shared__ float sU[8][420];
  __shared__ float sC[8][10], sS[8][10];
  __shared__ int   sP[8][10], sQ[8][10];
  __shared__ float sL[8][20];

  const int warp = threadIdx.x >> 5;
  const int lane = threadIdx.x & 31;
  const int b = blockIdx.x * 8 + warp;
  float* A = sA[warp];
  float* U = sU[warp];
  const float* Yb = g_Y + (size_t)b * 400;

  for (int o = lane; o < 400; o += 32) {
    const int i = o / 20, j = o - i * 20;
    A[i * 21 + j] = Yb[o];
  }
  for (int o = lane; o < 420; o += 32) U[o] = 0.f;
  __syncwarp();
  if (lane < 20) U[lane * 21 + lane] = 1.f;
  __syncwarp();

  for (int sw = 0; sw < NSWEEP; sw++) {
    for (int r = 0; r < 19; r++) {
      // --- 10 disjoint rotation angles from pre-round matrix ---
      if (lane < 10) {
        const int u = (lane == 0) ? 0 : ((lane - 1 + r) % 19) + 1;
        const int v = ((18 - lane + r) % 19) + 1;
        const int p = min(u, v), q = max(u, v);
        sP[warp][lane] = p;
        sQ[warp][lane] = q;
        const float apq = A[p * 21 + q];
        float c = 1.f, s = 0.f;
        if (fabsf(apq) > 1e-20f) {
          const float tau = (A[q * 21 + q] - A[p * 21 + p]) * (0.5f / apq);
          const float t = copysignf(1.f, tau) / (fabsf(tau) + sqrtf(1.f + tau * tau));
          c = rsqrtf(1.f + t * t);
          s = t * c;
        }
        sC[warp][lane] = c;
        sS[warp][lane] = s;
      }
      __syncwarp();
      // --- row phase: B = P^T A (disjoint rows, in-place safe) ---
      if (lane < 20) {
        const int j = lane;
#pragma unroll
        for (int i = 0; i < 10; i++) {
          const int p = sP[warp][i], q = sQ[warp][i];
          const float c = sC[warp][i], s = sS[warp][i];
          const float ap = A[p * 21 + j], aq = A[q * 21 + j];
          A[p * 21 + j] = c * ap - s * aq;
          A[q * 21 + j] = s * ap + c * aq;
        }
      }
      __syncwarp();
      // --- col phase: A = B P ; accumulate U = U P ---
      if (lane < 20) {
        const int rr = lane;
#pragma unroll
        for (int i = 0; i < 10; i++) {
          const int p = sP[warp][i], q = sQ[warp][i];
          const float c = sC[warp][i], s = sS[warp][i];
          const float ap = A[rr * 21 + p], aq = A[rr * 21 + q];
          A[rr * 21 + p] = c * ap - s * aq;
          A[rr * 21 + q] = s * ap + c * aq;
          const float up = U[rr * 21 + p], uq = U[rr * 21 + q];
          U[rr * 21 + p] = c * up - s * uq;
          U[rr * 21 + q] = s * up + c * uq;
        }
      }
      __syncwarp();
    }
  }

  if (lane < 20) sL[warp][lane] = logf(fmaxf(A[lane * 21 + lane], 1e-4f));
  __syncwarp();

  // A <- U * diag(logS)
  for (int o = lane; o < 400; o += 32) {
    const int i = o / 20, j = o - i * 20;
    A[i * 21 + j] = U[i * 21 + j] * sL[warp][j];
  }
  __syncwarp();

  // v[t] = M[i][k] (triu), fused with linear head: out = v @ lin_w^T + lin_b
  float accv[10];
#pragma unroll
  for (int h = 0; h < 10; h++) accv[h] = 0.f;

  for (int t = lane; t < 210; t += 32) {
    int i = 0, rem = t;
    while (rem >= 20 - i) { rem -= 20 - i; i++; }
    const int k = i + rem;
    float m = 0.f;
#pragma unroll
    for (int j = 0; j < 20; j++)
      m = fmaf(A[i * 21 + j], U[k * 21 + j], m);
#pragma unroll
    for (int h = 0; h < 10; h++)
      accv[h] = fmaf(m, lin_w[h * 210 + t], accv[h]);
  }
#pragma unroll
  for (int h = 0; h < 10; h++) {
    float v = accv[h];
    v += __shfl_xor_sync(0xffffffffu, v, 16);
    v += __shfl_xor_sync(0xffffffffu, v, 8);
    v += __shfl_xor_sync(0xffffffffu, v, 4);
    v += __shfl_xor_sync(0xffffffffu, v, 2);
    v += __shfl_xor_sync(0xffffffffu, v, 1);
    accv[h] = v;
  }
  if (lane == 0) {
#pragma unroll
    for (int h = 0; h < 10; h++) out[b * 10 + h] = accv[h] + lin_b[h];
  }
}

// ---------------------------------------------------------------------------
extern "C" void kernel_launch(void* const* d_in, const int* in_sizes, int n_in,
                              void* d_out, int out_size) {
  const float* x  = (const float*)d_in[0];
  const float* W  = (const float*)d_in[1];
  const float* lw = (const float*)d_in[2];
  const float* lb = (const float*)d_in[3];
  float* out = (float*)d_out;

  cudaFuncSetAttribute(gram_kernel, cudaFuncAttributeMaxDynamicSharedMemorySize,
                       23424 * sizeof(float));

  gram_kernel<<<4096, 256, 23424 * sizeof(float)>>>(x, W);
  eig_kernel<<<512, 256>>>(lw, lb, out);
}